// round 12
// baseline (speedup 1.0000x reference)
#include <cuda_runtime.h>
#include <cuda_bf16.h>
#include <math.h>
#include <stdint.h>

// Problem constants
#define B_  32
#define N_  4096
#define C_  512
#define EPS_INV 10.0f          // 1/EPS_SINKHORN

#define CHUNKS 16              // chunk-blocks per batch -> grid 512
#define ROWS_PER_BLOCK (N_ / CHUNKS)   // 256
#define THREADS1 256           // 8 warps
#define NWARPS (THREADS1 / 32)
#define ITERS (ROWS_PER_BLOCK / NWARPS)   // 32 rows per warp

#define STAGES 3               // per-warp ring stages
#define ROW_F4 (C_ / 4)        // 128 float4 = 2KB per row
// total smem = NWARPS * STAGES * ROW_F4 * 16B = 48KB exactly, 0 static

// Scratch (allocation-free rule: __device__ globals)
__device__ float        g_vec[B_ * CHUNKS * C_];   // partial weighted sums: 1 MB
__device__ float        g_E[B_ * CHUNKS];          // partial exp-sums
__device__ unsigned int g_cnt[B_];                 // zero-init; last block resets -> replayable

__device__ __forceinline__ void cp_async16(float4* smem_dst, const float4* gmem_src) {
    uint32_t s = (uint32_t)__cvta_generic_to_shared(smem_dst);
    asm volatile("cp.async.cg.shared.global [%0], [%1], 16;\n" :: "r"(s), "l"(gmem_src));
}
#define CP_COMMIT()  asm volatile("cp.async.commit_group;\n" ::: "memory")
#define CP_WAIT(n)   asm volatile("cp.async.wait_group %0;\n" :: "n"(n) : "memory")

// Two independent butterfly reductions, interleaved so the ~26-cyc SHFL
// latencies of the a- and b-chains overlap instead of serializing.
// (redux.sync.add.f32 does NOT exist on sm_103a — R11 compile fail.)
__device__ __forceinline__ void warp_sum2(float& a, float& b) {
    #pragma unroll
    for (int o = 16; o; o >>= 1) {
        float ta = __shfl_xor_sync(0xffffffffu, a, o);
        float tb = __shfl_xor_sync(0xffffffffu, b, o);
        a += ta;
        b += tb;
    }
}

// ---------------------------------------------------------------------------
// Fused single-pass kernel. Per-WARP private 3-stage cp.async pipelines:
// no __syncthreads in the main loop (cp.async group state is per-thread, and
// each lane reads back exactly the float4s it copied, so warps free-run).
// Last chunk-block per batch performs the cross-chunk combine.
//
// Per row: e = exp(10*(cos_sim - 1)) (shift m=0 valid since cos_sim <= 1),
// accumulate (e/|v|)*v and e. Softmax Z folds out analytically:
//   obs = num / (E + 1e-6*S),  total_mass = E / S,  S = E + exp(-10*dustbin).
// ---------------------------------------------------------------------------
__global__ __launch_bounds__(THREADS1, 4)
void uot_fused(const float* __restrict__ prompt,
               const float* __restrict__ vfeats,
               const float* __restrict__ dustbin_param,
               float* __restrict__ out)
{
    extern __shared__ float4 s_mem[];        // 48KB dynamic, 0 static

    const int b     = blockIdx.x / CHUNKS;
    const int chunk = blockIdx.x % CHUNKS;
    const int tid   = threadIdx.x;
    const int wid   = tid >> 5;
    const int lane  = tid & 31;

    // Warp wid's private ring: stages at s_ring + s*ROW_F4
    float4* s_ring = s_mem + (size_t)wid * STAGES * ROW_F4;

    const float* base = vfeats + ((size_t)b * N_ + (size_t)chunk * ROWS_PER_BLOCK) * C_;
    const float4* gbase = (const float4*)base;

    // ---- Prologue: each warp prefetches its first STAGES rows ----
    // Warp wid owns rows wid + t*NWARPS, t = 0..ITERS-1
    #pragma unroll
    for (int s = 0; s < STAGES; s++) {
        const float4* src = gbase + (size_t)(wid + s * NWARPS) * ROW_F4;
        float4* dst = s_ring + s * ROW_F4;
        #pragma unroll
        for (int k = 0; k < 4; k++)
            cp_async16(dst + lane + k * 32, src + lane + k * 32);
        CP_COMMIT();
    }

    // ---- Prompt into registers + its norm (overlaps prologue fetches) ----
    float4 p[4];
    {
        const float4* pr = (const float4*)(prompt + (size_t)b * C_);
        float ss = 0.f;
        #pragma unroll
        for (int j = 0; j < 4; j++) {
            p[j] = __ldg(pr + j * 32 + lane);
            ss += p[j].x * p[j].x + p[j].y * p[j].y + p[j].z * p[j].z + p[j].w * p[j].w;
        }
        float dummy = 0.f;
        warp_sum2(ss, dummy);
        float pinv = rsqrtf(fmaxf(ss, 1e-24f));
        #pragma unroll
        for (int j = 0; j < 4; j++) {        // pre-scale prompt by 1/|p|
            p[j].x *= pinv; p[j].y *= pinv; p[j].z *= pinv; p[j].w *= pinv;
        }
    }

    // ---- Main loop: warp-private, barrier-free ----
    float acc[16];
    #pragma unroll
    for (int i = 0; i < 16; i++) acc[i] = 0.f;
    float Eacc = 0.f;

    for (int t = 0; t < ITERS; t++) {
        CP_WAIT(STAGES - 1);                 // own oldest row landed

        const float4* rowp = s_ring + (t % STAGES) * ROW_F4;
        float4 v[4];
        float dpv = 0.f, dvv = 0.f;
        #pragma unroll
        for (int j = 0; j < 4; j++) v[j] = rowp[j * 32 + lane];  // own lanes' data
        #pragma unroll
        for (int j = 0; j < 4; j++) {
            dpv += v[j].x * p[j].x + v[j].y * p[j].y + v[j].z * p[j].z + v[j].w * p[j].w;
            dvv += v[j].x * v[j].x + v[j].y * v[j].y + v[j].z * v[j].z + v[j].w * v[j].w;
        }
        warp_sum2(dpv, dvv);

        float invn = rsqrtf(fmaxf(dvv, 1e-24f));
        float e    = __expf(EPS_INV * (dpv * invn - 1.0f));   // p already unit-norm
        float w    = e * invn;               // weight applied to the RAW row
        Eacc += e;
        #pragma unroll
        for (int j = 0; j < 4; j++) {
            acc[j * 4 + 0] += w * v[j].x;
            acc[j * 4 + 1] += w * v[j].y;
            acc[j * 4 + 2] += w * v[j].z;
            acc[j * 4 + 3] += w * v[j].w;
        }

        // Refill this stage with row t+STAGES (commit always, keeps counts aligned)
        const int tn = t + STAGES;
        if (tn < ITERS) {
            const float4* src = gbase + (size_t)(wid + tn * NWARPS) * ROW_F4;
            float4* dst = s_ring + (tn % STAGES) * ROW_F4;
            #pragma unroll
            for (int k = 0; k < 4; k++)
                cp_async16(dst + lane + k * 32, src + lane + k * 32);
        }
        CP_COMMIT();
    }

    // ---- Epilogue: one barrier, then reuse ring as cross-warp scratch ----
    CP_WAIT(0);                              // drain (remaining groups are empty)
    __syncthreads();                         // all warps done with their rings

    float* sacc  = (float*)s_mem;            // NWARPS*C_ floats = 16KB
    float* sEw   = sacc + NWARPS * C_;       // NWARPS floats
    float* sEtot = sEw + NWARPS;             // 1 float
    int*   sLast = (int*)(sEtot + 1);        // 1 int

    float4* sa4 = (float4*)(sacc + wid * C_);
    #pragma unroll
    for (int j = 0; j < 4; j++)
        sa4[j * 32 + lane] = make_float4(acc[j*4+0], acc[j*4+1], acc[j*4+2], acc[j*4+3]);
    if (lane == 0) sEw[wid] = Eacc;
    __syncthreads();

    const int slot = b * CHUNKS + chunk;
    #pragma unroll
    for (int c = tid; c < C_; c += THREADS1) {
        float s = 0.f;
        #pragma unroll
        for (int w = 0; w < NWARPS; w++) s += sacc[w * C_ + c];
        g_vec[slot * C_ + c] = s;
    }
    if (tid == 0) {
        float s = 0.f;
        #pragma unroll
        for (int w = 0; w < NWARPS; w++) s += sEw[w];
        g_E[slot] = s;
    }

    // ---- Last-block-per-batch does the final combine ----
    __syncthreads();
    if (tid == 0) {
        __threadfence();                     // release partials
        unsigned int old = atomicAdd(&g_cnt[b], 1u);
        *sLast = (old == CHUNKS - 1);
    }
    __syncthreads();
    if (!*sLast) return;
    __threadfence();                         // acquire others' partials

    if (tid < CHUNKS) {                      // CHUNKS == 16
        float e = g_E[b * CHUNKS + tid];
        #pragma unroll
        for (int o = CHUNKS / 2; o; o >>= 1)
            e += __shfl_xor_sync(0x0000ffffu, e, o);
        if (tid == 0) *sEtot = e;
    }
    __syncthreads();

    const float E    = *sEtot;
    const float ebin = __expf(-EPS_INV * dustbin_param[0]);
    const float S    = E + ebin;
    const float dinv = 1.0f / (E + 1e-6f * S);

    #pragma unroll
    for (int c = tid; c < C_; c += THREADS1) {
        float num = 0.f;
        #pragma unroll
        for (int ch = 0; ch < CHUNKS; ch++)
            num += g_vec[(b * CHUNKS + ch) * C_ + c];
        out[b * C_ + c] = num * dinv;
    }
    if (tid == 0) {
        out[B_ * C_ + b] = E / S;            // total_mass
        g_cnt[b] = 0;                        // reset for next graph replay
    }
}

// ---------------------------------------------------------------------------
extern "C" void kernel_launch(void* const* d_in, const int* in_sizes, int n_in,
                              void* d_out, int out_size)
{
    const float* prompt  = (const float*)d_in[0];   // (32,1,512)
    const float* vfeats  = (const float*)d_in[1];   // (32,4096,512)
    // d_in[2] = dustbin_token : unused by the reference computation
    const float* dparam  = (const float*)d_in[3];   // (1,)
    float* out = (float*)d_out;

    const int smem = NWARPS * STAGES * ROW_F4 * sizeof(float4);  // 49152B dynamic
    uot_fused<<<B_ * CHUNKS, THREADS1, smem>>>(prompt, vfeats, dparam, out);
}